// round 1
// baseline (speedup 1.0000x reference)
#include <cuda_runtime.h>
#include <math.h>

// Problem dims
#define T_STEPS 256
#define BATCH   64
#define DIM     512
#define HID     1024
#define G4      (4*HID)      // 4096 gate columns
#define KW      (DIM+HID)    // 1536 = W row length

// ---------------- device scratch (no runtime allocation allowed) ----------------
__device__ float g_gx[(size_t)T_STEPS * BATCH * G4];   // precomputed x-gates + bias, 256MB
__device__ float g_h[2 * BATCH * HID];                 // double-buffered hidden state
__device__ unsigned g_bar_count = 0;
__device__ volatile unsigned g_bar_sense = 0;

// ---------------- grid-wide barrier (sense reversal, self-cleaning) ----------------
__device__ __forceinline__ void grid_bar(unsigned nblocks) {
    __threadfence();              // make this thread's global writes visible chip-wide
    __syncthreads();
    if (threadIdx.x == 0) {
        unsigned s = g_bar_sense; // value for THIS barrier (proved monotone-consistent)
        unsigned old = atomicAdd(&g_bar_count, 1u);
        if (old == nblocks - 1u) {
            g_bar_count = 0u;     // self-clean for next barrier
            __threadfence();
            atomicAdd((unsigned*)&g_bar_sense, 1u);
        } else {
            while (g_bar_sense == s) { __nanosleep(32); }
        }
    }
    __syncthreads();
}

// =====================================================================
// Phase A: gx[m, gate*1024+u] = bias + sum_{k<512} X[m,k] * W[gate][u*1536+k]
// Tiled fp32 GEMM, BM=BN=64, BK=16, 256 threads, 4x4 per thread.
// =====================================================================
#define BM 64
#define BN 64
#define BK 16

__global__ __launch_bounds__(256) void gemm_x_kernel(
    const float* __restrict__ X,
    const float* __restrict__ Wf, const float* __restrict__ bfv,
    const float* __restrict__ Wi, const float* __restrict__ biv,
    const float* __restrict__ Wg, const float* __restrict__ bgv,
    const float* __restrict__ Wo, const float* __restrict__ bov)
{
    __shared__ float As[BK][BM + 1];
    __shared__ float Bs[BK][BN + 1];

    const int tid = threadIdx.x;
    const int tx = tid & 15;     // col group
    const int ty = tid >> 4;     // row group
    const int m0 = blockIdx.y * BM;
    const int n0 = blockIdx.x * BN;
    const int gate = n0 >> 10;          // 64 | 1024 -> tile never crosses gates
    const int u0 = n0 & 1023;

    const float* W    = (gate == 0) ? Wf  : (gate == 1) ? Wi  : (gate == 2) ? Wg  : Wo;
    const float* bias = (gate == 0) ? bfv : (gate == 1) ? biv : (gate == 2) ? bgv : bov;

    const int lrow = tid >> 2;   // 0..63
    const int lseg = tid & 3;    // 0..3 (k sub-segment of 4 floats)

    float acc[4][4];
#pragma unroll
    for (int i = 0; i < 4; i++)
#pragma unroll
        for (int j = 0; j < 4; j++) acc[i][j] = 0.f;

    for (int k0 = 0; k0 < DIM; k0 += BK) {
        float4 av = *(const float4*)(X + (size_t)(m0 + lrow) * DIM + k0 + lseg * 4);
        float4 bv = *(const float4*)(W + (size_t)(u0 + lrow) * KW  + k0 + lseg * 4);
        As[lseg * 4 + 0][lrow] = av.x;
        As[lseg * 4 + 1][lrow] = av.y;
        As[lseg * 4 + 2][lrow] = av.z;
        As[lseg * 4 + 3][lrow] = av.w;
        Bs[lseg * 4 + 0][lrow] = bv.x;
        Bs[lseg * 4 + 1][lrow] = bv.y;
        Bs[lseg * 4 + 2][lrow] = bv.z;
        Bs[lseg * 4 + 3][lrow] = bv.w;
        __syncthreads();
#pragma unroll
        for (int kk = 0; kk < BK; ++kk) {
            float a[4], b[4];
#pragma unroll
            for (int i = 0; i < 4; i++) a[i] = As[kk][ty * 4 + i];
#pragma unroll
            for (int j = 0; j < 4; j++) b[j] = Bs[kk][tx * 4 + j];
#pragma unroll
            for (int i = 0; i < 4; i++)
#pragma unroll
                for (int j = 0; j < 4; j++) acc[i][j] += a[i] * b[j];
        }
        __syncthreads();
    }

#pragma unroll
    for (int j = 0; j < 4; j++) {
        float bb = bias[u0 + tx * 4 + j];
#pragma unroll
        for (int i = 0; i < 4; i++) {
            size_t m = (size_t)(m0 + ty * 4 + i);
            g_gx[m * G4 + gate * HID + u0 + tx * 4 + j] = acc[i][j] + bb;
        }
    }
}

// =====================================================================
// Phase B: persistent recurrent kernel. grid=128 blocks (all resident),
// 128 threads/block. Block b owns hidden units [b*8, b*8+8) and all 4
// gates for them. Wh slice (32 cols x 1024 K = 128KB) lives in SMEM for
// all 256 steps. c lives in SMEM. One grid barrier per step.
// Column index within block: c = ui*4 + gate  (ui in [0,8), gate in [0,4))
// =====================================================================
#define RB_BLOCKS 128
#define RB_THREADS 128
#define WS_STRIDE 1025   // 1024 + 1 pad
#define HS_STRIDE 65     // 64 + 1 pad
#define KCHUNK 64

__global__ __launch_bounds__(RB_THREADS, 1) void lstm_rec_kernel(
    const float* __restrict__ Wf, const float* __restrict__ Wi,
    const float* __restrict__ Wg, const float* __restrict__ Wo,
    float* __restrict__ out, long long out_size)
{
    extern __shared__ float sm[];
    float* ws = sm;                               // 32 * 1025
    float* hs = ws + 32 * WS_STRIDE;              // 64 * 65
    float* cs = hs + 64 * HS_STRIDE;              // 64 * 8

    const int tid = threadIdx.x;
    const int tx = tid & 7;      // local unit (ui), 0..7
    const int ty = tid >> 3;     // row group, 0..15 (4 rows each)
    const int u0 = blockIdx.x * 8;

    // Load Wh slice into shared: ws[(ui*4+gate)*WS_STRIDE + k] = W[gate][(u0+ui)*KW + 512 + k]
    {
        const float* Wp0 = Wf; const float* Wp1 = Wi; const float* Wp2 = Wg; const float* Wp3 = Wo;
        for (int idx = tid; idx < 32 * 1024; idx += RB_THREADS) {
            int c = idx >> 10;
            int k = idx & 1023;
            int gate = c & 3;
            int ui = c >> 2;
            const float* Wp = (gate == 0) ? Wp0 : (gate == 1) ? Wp1 : (gate == 2) ? Wp2 : Wp3;
            ws[c * WS_STRIDE + k] = Wp[(size_t)(u0 + ui) * KW + DIM + k];
        }
    }
    for (int idx = tid; idx < 64 * 8; idx += RB_THREADS) cs[idx] = 0.f;
    __syncthreads();

    const float* wsp_base = ws + (tx * 4) * WS_STRIDE;
    const float* hsp = hs + (ty * 4) * HS_STRIDE;

    for (int t = 0; t < T_STEPS; ++t) {
        float acc[4][4];
#pragma unroll
        for (int i = 0; i < 4; i++)
#pragma unroll
            for (int j = 0; j < 4; j++) acc[i][j] = 0.f;

        if (t > 0) {
            const float* hsrc = g_h + (size_t)((t - 1) & 1) * (BATCH * HID);
            for (int kc = 0; kc < HID; kc += KCHUNK) {
                // stage h chunk [64 rows x 64 k] into shared (L2-only loads: h changes every step)
                for (int idx = tid; idx < BATCH * KCHUNK; idx += RB_THREADS) {
                    int r = idx >> 6;
                    int k = idx & 63;
                    hs[r * HS_STRIDE + k] = __ldcg(hsrc + (size_t)r * HID + kc + k);
                }
                __syncthreads();
                const float* wsp = wsp_base + kc;
#pragma unroll 8
                for (int k = 0; k < KCHUNK; ++k) {
                    float a0 = hsp[0 * HS_STRIDE + k];
                    float a1 = hsp[1 * HS_STRIDE + k];
                    float a2 = hsp[2 * HS_STRIDE + k];
                    float a3 = hsp[3 * HS_STRIDE + k];
                    float b0 = wsp[0 * WS_STRIDE + k];
                    float b1 = wsp[1 * WS_STRIDE + k];
                    float b2 = wsp[2 * WS_STRIDE + k];
                    float b3 = wsp[3 * WS_STRIDE + k];
                    acc[0][0] += a0 * b0; acc[0][1] += a0 * b1; acc[0][2] += a0 * b2; acc[0][3] += a0 * b3;
                    acc[1][0] += a1 * b0; acc[1][1] += a1 * b1; acc[1][2] += a1 * b2; acc[1][3] += a1 * b3;
                    acc[2][0] += a2 * b0; acc[2][1] += a2 * b1; acc[2][2] += a2 * b2; acc[2][3] += a2 * b3;
                    acc[3][0] += a3 * b0; acc[3][1] += a3 * b1; acc[3][2] += a3 * b2; acc[3][3] += a3 * b3;
                }
                __syncthreads();
            }
        }

        // gates + state update for 4 rows, 1 unit, all 4 gates (thread-local combine)
        const float* gx = g_gx + (size_t)t * BATCH * G4;
        float* hdst = g_h + (size_t)(t & 1) * (BATCH * HID);
#pragma unroll
        for (int i = 0; i < 4; i++) {
            int row = ty * 4 + i;
            const float* gxr = gx + (size_t)row * G4 + u0 + tx;
            float gf = acc[i][0] + gxr[0 * HID];
            float gi = acc[i][1] + gxr[1 * HID];
            float gg = acc[i][2] + gxr[2 * HID];
            float go = acc[i][3] + gxr[3 * HID];

            float fg = 1.f / (1.f + expf(-gf));
            float ig = 1.f / (1.f + expf(-gi));
            float g  = tanhf(gg);
            float og = 1.f / (1.f + expf(-go));

            float c_old = cs[row * 8 + tx];
            float c_new = fg * c_old + ig * g;
            float h_new = og * tanhf(c_new);
            cs[row * 8 + tx] = c_new;

            size_t hoff = (size_t)row * HID + u0 + tx;
            hdst[hoff] = h_new;
            out[(size_t)t * (BATCH * HID) + hoff] = h_new;

            if (t == T_STEPS - 1) {
                long long base = (long long)T_STEPS * BATCH * HID;
                long long ho = base + (long long)hoff;
                long long co = base + (long long)(BATCH * HID) + (long long)hoff;
                if (ho < out_size) out[ho] = h_new;
                if (co < out_size) out[co] = c_new;
            }
        }

        if (t < T_STEPS - 1) grid_bar(RB_BLOCKS);
    }
}

// =====================================================================
extern "C" void kernel_launch(void* const* d_in, const int* in_sizes, int n_in,
                              void* d_out, int out_size)
{
    const float* inputs = (const float*)d_in[0];
    const float* Wf = (const float*)d_in[1];
    const float* bf = (const float*)d_in[2];
    const float* Wi = (const float*)d_in[3];
    const float* bi = (const float*)d_in[4];
    const float* Wg = (const float*)d_in[5];
    const float* bg = (const float*)d_in[6];
    const float* Wo = (const float*)d_in[7];
    const float* bo = (const float*)d_in[8];
    float* out = (float*)d_out;

    // Phase A: precompute x-gates (+bias) for all timesteps
    dim3 gridA(G4 / BN, (T_STEPS * BATCH) / BM);
    gemm_x_kernel<<<gridA, 256>>>(inputs, Wf, bf, Wi, bi, Wg, bg, Wo, bo);

    // Phase B: persistent recurrence
    int smem_bytes = (32 * WS_STRIDE + 64 * HS_STRIDE + 64 * 8) * (int)sizeof(float);
    cudaFuncSetAttribute(lstm_rec_kernel, cudaFuncAttributeMaxDynamicSharedMemorySize, smem_bytes);
    lstm_rec_kernel<<<RB_BLOCKS, RB_THREADS, smem_bytes>>>(Wf, Wi, Wg, Wo, out, (long long)out_size);
}

// round 2
// speedup vs baseline: 2.5126x; 2.5126x over previous
#include <cuda_runtime.h>
#include <math.h>

// Problem dims
#define T_STEPS 256
#define BATCH   64
#define DIM     512
#define HID     1024
#define G4      (4*HID)      // 4096 gate columns
#define KW      (DIM+HID)    // 1536 = W row length

// ---------------- device scratch ----------------
__device__ float g_gx[(size_t)T_STEPS * BATCH * G4];   // precomputed x-gates + bias
__device__ float g_h[2 * BATCH * HID];                 // double-buffered hidden state
__device__ unsigned g_bar_count = 0;
__device__ volatile unsigned g_bar_sense = 0;

// ---------------- packed f32x2 helpers ----------------
__device__ __forceinline__ unsigned long long pk2(float lo, float hi) {
    unsigned long long r;
    asm("mov.b64 %0, {%1, %2};" : "=l"(r) : "f"(lo), "f"(hi));
    return r;
}
__device__ __forceinline__ void upk2(unsigned long long v, float& lo, float& hi) {
    asm("mov.b64 {%0, %1}, %2;" : "=f"(lo), "=f"(hi) : "l"(v));
}
__device__ __forceinline__ unsigned long long ffma2(unsigned long long a,
                                                    unsigned long long b,
                                                    unsigned long long c) {
    unsigned long long d;
    asm("fma.rn.f32x2 %0, %1, %2, %3;" : "=l"(d) : "l"(a), "l"(b), "l"(c));
    return d;
}

// ---------------- split grid barrier (sense reversal) ----------------
__device__ __forceinline__ void grid_arrive(unsigned nblocks, unsigned& s) {
    __threadfence();
    __syncthreads();
    if (threadIdx.x == 0) {
        s = g_bar_sense;
        unsigned old = atomicAdd(&g_bar_count, 1u);
        if (old == nblocks - 1u) {
            g_bar_count = 0u;
            __threadfence();
            atomicAdd((unsigned*)&g_bar_sense, 1u);
        }
    }
}
__device__ __forceinline__ void grid_wait(unsigned s) {
    if (threadIdx.x == 0) {
        while (g_bar_sense == s) { __nanosleep(32); }
    }
    __syncthreads();
}

// =====================================================================
// Phase A: gx[m, gate*1024+u] = bias + sum_{k<512} X[m,k] * W[gate][u*1536+k]
// 128x128x16 tiles, 256 threads, 8x8 per thread via FFMA2 (f32x2).
// =====================================================================
#define A_BK 16
#define A_STRIDE 132

__global__ __launch_bounds__(256, 2) void gemm_x_kernel(
    const float* __restrict__ X,
    const float* __restrict__ Wf, const float* __restrict__ bfv,
    const float* __restrict__ Wi, const float* __restrict__ biv,
    const float* __restrict__ Wg, const float* __restrict__ bgv,
    const float* __restrict__ Wo, const float* __restrict__ bov)
{
    __shared__ float As[A_BK * A_STRIDE];
    __shared__ float Bs[A_BK * A_STRIDE];

    const int tid = threadIdx.x;
    const int tx = tid & 15;    // 8 cols each
    const int ty = tid >> 4;    // 8 rows each
    const int m0 = blockIdx.y * 128;
    const int n0 = blockIdx.x * 128;
    const int gate = n0 >> 10;
    const int u0 = n0 & 1023;

    const float* W    = (gate == 0) ? Wf  : (gate == 1) ? Wi  : (gate == 2) ? Wg  : Wo;
    const float* bias = (gate == 0) ? bfv : (gate == 1) ? biv : (gate == 2) ? bgv : bov;

    unsigned long long acc2[8][4];
#pragma unroll
    for (int i = 0; i < 8; i++)
#pragma unroll
        for (int p = 0; p < 4; p++) acc2[i][p] = 0ull;  // {0.f,0.f}

    for (int k0 = 0; k0 < DIM; k0 += A_BK) {
        // stage A (transpose to k-major) and B
#pragma unroll
        for (int p = 0; p < 2; p++) {
            int e = p * 256 + tid;
            int r = e >> 2;          // 0..127
            int q = e & 3;           // float4 slot within 16 k
            float4 xv = *(const float4*)(X + (size_t)(m0 + r) * DIM + k0 + q * 4);
            As[(q * 4 + 0) * A_STRIDE + r] = xv.x;
            As[(q * 4 + 1) * A_STRIDE + r] = xv.y;
            As[(q * 4 + 2) * A_STRIDE + r] = xv.z;
            As[(q * 4 + 3) * A_STRIDE + r] = xv.w;
            float4 wv = *(const float4*)(W + (size_t)(u0 + r) * KW + k0 + q * 4);
            Bs[(q * 4 + 0) * A_STRIDE + r] = wv.x;
            Bs[(q * 4 + 1) * A_STRIDE + r] = wv.y;
            Bs[(q * 4 + 2) * A_STRIDE + r] = wv.z;
            Bs[(q * 4 + 3) * A_STRIDE + r] = wv.w;
        }
        __syncthreads();
#pragma unroll
        for (int kk = 0; kk < A_BK; ++kk) {
            const float* ar = As + kk * A_STRIDE + ty * 8;
            float4 a0 = *(const float4*)ar;
            float4 a1 = *(const float4*)(ar + 4);
            const float* br = Bs + kk * A_STRIDE + tx * 8;
            float4 b0 = *(const float4*)br;
            float4 b1 = *(const float4*)(br + 4);
            unsigned long long bp0 = pk2(b0.x, b0.y);
            unsigned long long bp1 = pk2(b0.z, b0.w);
            unsigned long long bp2 = pk2(b1.x, b1.y);
            unsigned long long bp3 = pk2(b1.z, b1.w);
            float av[8] = {a0.x, a0.y, a0.z, a0.w, a1.x, a1.y, a1.z, a1.w};
#pragma unroll
            for (int i = 0; i < 8; i++) {
                unsigned long long ad = pk2(av[i], av[i]);
                acc2[i][0] = ffma2(ad, bp0, acc2[i][0]);
                acc2[i][1] = ffma2(ad, bp1, acc2[i][1]);
                acc2[i][2] = ffma2(ad, bp2, acc2[i][2]);
                acc2[i][3] = ffma2(ad, bp3, acc2[i][3]);
            }
        }
        __syncthreads();
    }

    // epilogue: bias add + vectorized store
    float4 bb0 = *(const float4*)(bias + u0 + tx * 8);
    float4 bb1 = *(const float4*)(bias + u0 + tx * 8 + 4);
    float bb[8] = {bb0.x, bb0.y, bb0.z, bb0.w, bb1.x, bb1.y, bb1.z, bb1.w};
#pragma unroll
    for (int i = 0; i < 8; i++) {
        float o[8];
#pragma unroll
        for (int p = 0; p < 4; p++) upk2(acc2[i][p], o[2 * p], o[2 * p + 1]);
#pragma unroll
        for (int j = 0; j < 8; j++) o[j] += bb[j];
        size_t m = (size_t)(m0 + ty * 8 + i);
        float* dst = g_gx + m * G4 + gate * HID + u0 + tx * 8;
        *(float4*)dst       = make_float4(o[0], o[1], o[2], o[3]);
        *(float4*)(dst + 4) = make_float4(o[4], o[5], o[6], o[7]);
    }
}

// =====================================================================
// Phase B: persistent recurrence. 128 blocks x 512 threads.
// Block owns 8 hidden units (32 gate-columns). 4 K-groups of 128 threads
// each cover a 256-wide K slice; partials reduced through shared memory.
// Weights k-major in shared, adjacent-column pairs consumed by FFMA2.
// =====================================================================
#define RB_BLOCKS 128
#define RB_THREADS 512
#define KCHUNK 32
#define HS_STRIDE 33               // KCHUNK + 1
#define HS_GROUP (64 * HS_STRIDE)  // 2112 floats per group

__global__ __launch_bounds__(RB_THREADS, 1) void lstm_rec_kernel(
    const float* __restrict__ Wf, const float* __restrict__ Wi,
    const float* __restrict__ Wg, const float* __restrict__ Wo,
    float* __restrict__ out, long long out_size)
{
    extern __shared__ float sm[];
    float* wsf   = sm;               // [1024][32] k-major weights (128KB)
    float* hsall = sm + 1024 * 32;   // 4 groups x [64][33] h staging (33.8KB), aliased as red

    const int tid  = threadIdx.x;
    const int g    = tid >> 7;       // K-group 0..3
    const int wtid = tid & 127;
    const int tx   = wtid & 7;       // unit within block (cols 4tx..4tx+3)
    const int ty   = wtid >> 3;      // row group 0..15 (rows 4ty..4ty+3)
    const int u0   = blockIdx.x * 8;

    // final-mapping (state update): one (row, unit) per thread
    const int frow = tid >> 3;       // 0..63
    const int fu   = tid & 7;        // 0..7

    // ---- fill weights: wsf[k*32 + c] = W[gate][(u0+ui)*KW + 512 + k], c=ui*4+gate ----
    for (int idx = tid; idx < 32 * 1024; idx += RB_THREADS) {
        int c = idx & 31;
        int k = idx >> 5;
        int gate = c & 3;
        int ui = c >> 2;
        const float* Wp = (gate == 0) ? Wf : (gate == 1) ? Wi : (gate == 2) ? Wg : Wo;
        wsf[k * 32 + c] = Wp[(size_t)(u0 + ui) * KW + DIM + k];
    }
    __syncthreads();

    float* hsg = hsall + g * HS_GROUP;
    const float* hsrow = hsg + (ty * 4) * HS_STRIDE;
    float* red = hsall;              // alias (used after block sync)

    float c_reg = 0.f;
    unsigned bar_sense_local = 0;

    for (int t = 0; t < T_STEPS; ++t) {
        // prefetch gx for this thread's 4 gates (DRAM, consumed at step end)
        const float* gx_t = g_gx + (size_t)t * BATCH * G4;
        float gxv[4];
#pragma unroll
        for (int gt = 0; gt < 4; gt++)
            gxv[gt] = __ldcg(gx_t + (size_t)frow * G4 + gt * HID + u0 + fu);

        unsigned long long acc2[4][2];
#pragma unroll
        for (int i = 0; i < 4; i++) { acc2[i][0] = 0ull; acc2[i][1] = 0ull; }

        if (t > 0) {
            const float* hsrc = g_h + (size_t)((t - 1) & 1) * (BATCH * HID);
            const int kbase = g * 256;
#pragma unroll 1
            for (int cc = 0; cc < 256 / KCHUNK; ++cc) {
                int kc = kbase + cc * KCHUNK;
                // stage h[0..64)[kc..kc+32) into group buffer (L2 loads)
#pragma unroll
                for (int p = 0; p < 4; p++) {
                    int e = p * 128 + wtid;
                    int r = e >> 3;
                    int k4 = e & 7;
                    float4 v = __ldcg((const float4*)(hsrc + (size_t)r * HID + kc + k4 * 4));
                    float* d = hsg + r * HS_STRIDE + k4 * 4;
                    d[0] = v.x; d[1] = v.y; d[2] = v.z; d[3] = v.w;
                }
                asm volatile("bar.sync %0, %1;" :: "r"(g + 1), "r"(128) : "memory");
#pragma unroll 8
                for (int kk = 0; kk < KCHUNK; ++kk) {
                    ulonglong2 wv = *(const ulonglong2*)(wsf + (kc + kk) * 32 + tx * 4);
                    float h0 = hsrow[0 * HS_STRIDE + kk];
                    float h1 = hsrow[1 * HS_STRIDE + kk];
                    float h2 = hsrow[2 * HS_STRIDE + kk];
                    float h3 = hsrow[3 * HS_STRIDE + kk];
                    unsigned long long a0 = pk2(h0, h0);
                    unsigned long long a1 = pk2(h1, h1);
                    unsigned long long a2 = pk2(h2, h2);
                    unsigned long long a3 = pk2(h3, h3);
                    acc2[0][0] = ffma2(a0, wv.x, acc2[0][0]);
                    acc2[0][1] = ffma2(a0, wv.y, acc2[0][1]);
                    acc2[1][0] = ffma2(a1, wv.x, acc2[1][0]);
                    acc2[1][1] = ffma2(a1, wv.y, acc2[1][1]);
                    acc2[2][0] = ffma2(a2, wv.x, acc2[2][0]);
                    acc2[2][1] = ffma2(a2, wv.y, acc2[2][1]);
                    acc2[3][0] = ffma2(a3, wv.x, acc2[3][0]);
                    acc2[3][1] = ffma2(a3, wv.y, acc2[3][1]);
                }
                asm volatile("bar.sync %0, %1;" :: "r"(g + 1), "r"(128) : "memory");
            }
        }

        __syncthreads();   // all groups done reading hs -> safe to alias as red
        if (t > 0) {
#pragma unroll
            for (int i = 0; i < 4; i++) {
                float f0, f1, f2, f3;
                upk2(acc2[i][0], f0, f1);
                upk2(acc2[i][1], f2, f3);
                float* rp = red + g * 2048 + (ty * 4 + i) * 32 + tx * 4;
                rp[0] = f0; rp[1] = f1; rp[2] = f2; rp[3] = f3;
            }
            __syncthreads();
        }

        // ---- state update: thread handles (frow, fu) with all 4 gates ----
        float gate_v[4];
#pragma unroll
        for (int gt = 0; gt < 4; gt++) {
            float s = 0.f;
            if (t > 0) {
                int v = frow * 32 + fu * 4 + gt;
                s = red[v] + red[2048 + v] + red[4096 + v] + red[6144 + v];
            }
            gate_v[gt] = s + gxv[gt];
        }
        float fg = 1.f / (1.f + __expf(-gate_v[0]));
        float ig = 1.f / (1.f + __expf(-gate_v[1]));
        float gg = 2.f / (1.f + __expf(-2.f * gate_v[2])) - 1.f;   // tanh
        float og = 1.f / (1.f + __expf(-gate_v[3]));

        float c_new = fg * c_reg + ig * gg;
        float th = 2.f / (1.f + __expf(-2.f * c_new)) - 1.f;       // tanh(c)
        float h_new = og * th;
        c_reg = c_new;

        size_t hoff = (size_t)frow * HID + u0 + fu;
        float* hdst = g_h + (size_t)(t & 1) * (BATCH * HID);
        hdst[hoff] = h_new;

        if (t < T_STEPS - 1) {
            grid_arrive(RB_BLOCKS, bar_sense_local);
            out[(size_t)t * (BATCH * HID) + hoff] = h_new;   // overlap with barrier
            grid_wait(bar_sense_local);
        } else {
            out[(size_t)t * (BATCH * HID) + hoff] = h_new;
            long long base = (long long)T_STEPS * BATCH * HID;
            long long ho = base + (long long)hoff;
            long long co = base + (long long)(BATCH * HID) + (long long)hoff;
            if (ho < out_size) out[ho] = h_new;
            if (co < out_size) out[co] = c_new;
        }
    }
}

// =====================================================================
extern "C" void kernel_launch(void* const* d_in, const int* in_sizes, int n_in,
                              void* d_out, int out_size)
{
    const float* inputs = (const float*)d_in[0];
    const float* Wf = (const float*)d_in[1];
    const float* bf = (const float*)d_in[2];
    const float* Wi = (const float*)d_in[3];
    const float* bi = (const float*)d_in[4];
    const float* Wg = (const float*)d_in[5];
    const float* bg = (const float*)d_in[6];
    const float* Wo = (const float*)d_in[7];
    const float* bo = (const float*)d_in[8];
    float* out = (float*)d_out;

    // Phase A: precompute x-gates (+bias) for all timesteps
    dim3 gridA(G4 / 128, (T_STEPS * BATCH) / 128);
    gemm_x_kernel<<<gridA, 256>>>(inputs, Wf, bf, Wi, bi, Wg, bg, Wo, bo);

    // Phase B: persistent recurrence
    int smem_bytes = (1024 * 32 + 4 * HS_GROUP) * (int)sizeof(float);
    cudaFuncSetAttribute(lstm_rec_kernel, cudaFuncAttributeMaxDynamicSharedMemorySize, smem_bytes);
    lstm_rec_kernel<<<RB_BLOCKS, RB_THREADS, smem_bytes>>>(Wf, Wi, Wg, Wo, out, (long long)out_size);
}

// round 8
// speedup vs baseline: 3.6469x; 1.4515x over previous
#include <cuda_runtime.h>
#include <cstdint>
#include <math.h>

// Problem dims
#define T_STEPS 256
#define BATCH   64
#define DIM     512
#define HID     1024
#define G4      (4*HID)
#define KW      (DIM+HID)

// ---------------- device scratch ----------------
__device__ float g_gx[(size_t)T_STEPS * BATCH * G4];
__device__ float g_h[2 * BATCH * HID];
__device__ unsigned g_bar_count = 0;
__device__ volatile unsigned g_bar_sense = 0;

// ---------------- packed f32x2 helpers (Phase A) ----------------
__device__ __forceinline__ unsigned long long pk2(float lo, float hi) {
    unsigned long long r;
    asm("mov.b64 %0, {%1, %2};" : "=l"(r) : "f"(lo), "f"(hi));
    return r;
}
__device__ __forceinline__ void upk2(unsigned long long v, float& lo, float& hi) {
    asm("mov.b64 {%0, %1}, %2;" : "=f"(lo), "=f"(hi) : "l"(v));
}
__device__ __forceinline__ unsigned long long ffma2(unsigned long long a,
                                                    unsigned long long b,
                                                    unsigned long long c) {
    unsigned long long d;
    asm("fma.rn.f32x2 %0, %1, %2, %3;" : "=l"(d) : "l"(a), "l"(b), "l"(c));
    return d;
}

// ---------------- grid barrier (split arrive/wait) ----------------
__device__ __forceinline__ void grid_arrive(unsigned nblocks, unsigned& s) {
    __threadfence();
    __syncthreads();
    if (threadIdx.x == 0) {
        s = g_bar_sense;
        unsigned old = atomicAdd(&g_bar_count, 1u);
        if (old == nblocks - 1u) {
            g_bar_count = 0u;
            __threadfence();
            atomicAdd((unsigned*)&g_bar_sense, 1u);
        }
    }
}
__device__ __forceinline__ void grid_wait(unsigned s) {
    if (threadIdx.x == 0) {
        while (g_bar_sense == s) { __nanosleep(32); }
    }
    __syncthreads();
}

// ---------------- mma.sync tf32 helpers ----------------
__device__ __forceinline__ uint32_t smem_u32(const void* p) {
    uint32_t a;
    asm("{ .reg .u64 t; cvta.to.shared.u64 t, %1; cvt.u32.u64 %0, t; }" : "=r"(a) : "l"(p));
    return a;
}
__device__ __forceinline__ uint32_t f2tf32(float f) {
    uint32_t r;
    asm("cvt.rna.tf32.f32 %0, %1;" : "=r"(r) : "f"(f));
    return r;
}
__device__ __forceinline__ void mma_tf32(float* d,
                                         uint32_t a0, uint32_t a1, uint32_t a2, uint32_t a3,
                                         uint32_t b0, uint32_t b1) {
    asm volatile(
        "mma.sync.aligned.m16n8k8.row.col.f32.tf32.tf32.f32 "
        "{%0,%1,%2,%3}, {%4,%5,%6,%7}, {%8,%9}, {%0,%1,%2,%3};"
        : "+f"(d[0]), "+f"(d[1]), "+f"(d[2]), "+f"(d[3])
        : "r"(a0), "r"(a1), "r"(a2), "r"(a3), "r"(b0), "r"(b1));
}
__device__ __forceinline__ void cp16(uint32_t dst, const void* src) {
    asm volatile("cp.async.cg.shared.global [%0], [%1], 16;" :: "r"(dst), "l"(src));
}
#define CP_COMMIT() asm volatile("cp.async.commit_group;" ::: "memory")
#define CP_WAIT(n)  asm volatile("cp.async.wait_group %0;" :: "n"(n) : "memory")

// =====================================================================
// Phase A: gx = X @ Wx^T + b   (FFMA2, 128x128x16 tiles)
// =====================================================================
#define A_BK 16
#define A_STRIDE 132

__global__ __launch_bounds__(256, 2) void gemm_x_kernel(
    const float* __restrict__ X,
    const float* __restrict__ Wf, const float* __restrict__ bfv,
    const float* __restrict__ Wi, const float* __restrict__ biv,
    const float* __restrict__ Wg, const float* __restrict__ bgv,
    const float* __restrict__ Wo, const float* __restrict__ bov)
{
    __shared__ float As[A_BK * A_STRIDE];
    __shared__ float Bs[A_BK * A_STRIDE];

    const int tid = threadIdx.x;
    const int tx = tid & 15;
    const int ty = tid >> 4;
    const int m0 = blockIdx.y * 128;
    const int n0 = blockIdx.x * 128;
    const int gate = n0 >> 10;
    const int u0 = n0 & 1023;

    const float* W    = (gate == 0) ? Wf  : (gate == 1) ? Wi  : (gate == 2) ? Wg  : Wo;
    const float* bias = (gate == 0) ? bfv : (gate == 1) ? biv : (gate == 2) ? bgv : bov;

    unsigned long long acc2[8][4];
#pragma unroll
    for (int i = 0; i < 8; i++)
#pragma unroll
        for (int p = 0; p < 4; p++) acc2[i][p] = 0ull;

    for (int k0 = 0; k0 < DIM; k0 += A_BK) {
#pragma unroll
        for (int p = 0; p < 2; p++) {
            int e = p * 256 + tid;
            int r = e >> 2;
            int q = e & 3;
            float4 xv = *(const float4*)(X + (size_t)(m0 + r) * DIM + k0 + q * 4);
            As[(q * 4 + 0) * A_STRIDE + r] = xv.x;
            As[(q * 4 + 1) * A_STRIDE + r] = xv.y;
            As[(q * 4 + 2) * A_STRIDE + r] = xv.z;
            As[(q * 4 + 3) * A_STRIDE + r] = xv.w;
            float4 wv = *(const float4*)(W + (size_t)(u0 + r) * KW + k0 + q * 4);
            Bs[(q * 4 + 0) * A_STRIDE + r] = wv.x;
            Bs[(q * 4 + 1) * A_STRIDE + r] = wv.y;
            Bs[(q * 4 + 2) * A_STRIDE + r] = wv.z;
            Bs[(q * 4 + 3) * A_STRIDE + r] = wv.w;
        }
        __syncthreads();
#pragma unroll
        for (int kk = 0; kk < A_BK; ++kk) {
            const float* ar = As + kk * A_STRIDE + ty * 8;
            float4 a0 = *(const float4*)ar;
            float4 a1 = *(const float4*)(ar + 4);
            const float* br = Bs + kk * A_STRIDE + tx * 8;
            float4 b0 = *(const float4*)br;
            float4 b1 = *(const float4*)(br + 4);
            unsigned long long bp0 = pk2(b0.x, b0.y);
            unsigned long long bp1 = pk2(b0.z, b0.w);
            unsigned long long bp2 = pk2(b1.x, b1.y);
            unsigned long long bp3 = pk2(b1.z, b1.w);
            float av[8] = {a0.x, a0.y, a0.z, a0.w, a1.x, a1.y, a1.z, a1.w};
#pragma unroll
            for (int i = 0; i < 8; i++) {
                unsigned long long ad = pk2(av[i], av[i]);
                acc2[i][0] = ffma2(ad, bp0, acc2[i][0]);
                acc2[i][1] = ffma2(ad, bp1, acc2[i][1]);
                acc2[i][2] = ffma2(ad, bp2, acc2[i][2]);
                acc2[i][3] = ffma2(ad, bp3, acc2[i][3]);
            }
        }
        __syncthreads();
    }

    float4 bb0 = *(const float4*)(bias + u0 + tx * 8);
    float4 bb1 = *(const float4*)(bias + u0 + tx * 8 + 4);
    float bb[8] = {bb0.x, bb0.y, bb0.z, bb0.w, bb1.x, bb1.y, bb1.z, bb1.w};
#pragma unroll
    for (int i = 0; i < 8; i++) {
        float o[8];
#pragma unroll
        for (int p = 0; p < 4; p++) upk2(acc2[i][p], o[2 * p], o[2 * p + 1]);
#pragma unroll
        for (int j = 0; j < 8; j++) o[j] += bb[j];
        size_t m = (size_t)(m0 + ty * 8 + i);
        float* dst = g_gx + m * G4 + gate * HID + u0 + tx * 8;
        *(float4*)dst       = make_float4(o[0], o[1], o[2], o[3]);
        *(float4*)(dst + 4) = make_float4(o[4], o[5], o[6], o[7]);
    }
}

// =====================================================================
// Phase B: persistent recurrence with legacy mma.sync tf32 (2xTF32 on h).
// 128 blocks x 256 threads (8 warps). Block owns 32 gate-cols
// (units u0..u0+7, col c = ui*4+gate). Warp g owns K-slice [128g,128g+128):
// weights register-resident for all steps; h staged via cp.async.cg into
// per-warp double buffers; partials reduced through shared memory.
// =====================================================================
#define RB_BLOCKS 128
#define RB_THREADS 256

#define STG_BUF  (64 * 36)             // one chunk buffer: 64 rows x 36 pad floats
#define STG_WARP (2 * STG_BUF)         // double buffered
#define RED_OFF  (8 * STG_WARP)        // 36864 floats
#define RED_WARP (64 * 34)             // 2176 floats per warp region
#define SMF_TOTAL (RED_OFF + 8 * RED_WARP)   // 54272 floats = 217088 bytes

__global__ __launch_bounds__(RB_THREADS, 1) void lstm_rec_kernel(
    const float* __restrict__ Wf, const float* __restrict__ Wi,
    const float* __restrict__ Wg, const float* __restrict__ Wo,
    float* __restrict__ out, long long out_size)
{
    extern __shared__ float smf[];
    const int tid  = threadIdx.x;
    const int g    = tid >> 5;          // warp id 0..7 (K-slice owner)
    const int lane = tid & 31;
    const int r4   = lane >> 2;         // 0..7
    const int j    = lane & 3;          // 0..3
    const int u0   = blockIdx.x * 8;

    const uint32_t stg_u32 = smem_u32(smf);

    // ---- load weight fragments into registers (once) ----
    // b tile (kt in 0..15 within warp slice, nt in 0..3): col = nt*8 + r4,
    // k = g*128 + kt*8 + j (+4 for second reg)
    uint32_t bfr[16][4][2];
#pragma unroll
    for (int nt = 0; nt < 4; nt++) {
        int col = nt * 8 + r4;
        int gate = col & 3;
        int ui = col >> 2;
        const float* Wq = (gate == 0) ? Wf : (gate == 1) ? Wi : (gate == 2) ? Wg : Wo;
        const float* wrow = Wq + (size_t)(u0 + ui) * KW + DIM + g * 128 + j;
#pragma unroll
        for (int kt = 0; kt < 16; kt++) {
            bfr[kt][nt][0] = f2tf32(__ldg(wrow + kt * 8));
            bfr[kt][nt][1] = f2tf32(__ldg(wrow + kt * 8 + 4));
        }
    }

    // epilogue mapping: thread -> (row, unit-pair)
    const int erow = tid >> 2;          // 0..63
    const int eup  = tid & 3;           // 0..3 -> units 2eup, 2eup+1 (local)

    float c_reg0 = 0.f, c_reg1 = 0.f;
    unsigned bar_s = 0;

#define ISSUE_CHUNK(CC) do {                                                   \
    uint32_t dbase = stg_u32 + (uint32_t)((g * STG_WARP + ((CC) & 1) * STG_BUF) * 4); \
    const float* hs_ = hsrc + g * 128 + (CC) * 32;                             \
    _Pragma("unroll")                                                          \
    for (int q = 0; q < 16; q++) {                                             \
        int idx = q * 32 + lane;                                               \
        int row = idx >> 3;                                                    \
        int k4 = idx & 7;                                                      \
        cp16(dbase + (uint32_t)((row * 36 + k4 * 4) * 4),                      \
             hs_ + (size_t)row * HID + k4 * 4);                                \
    }                                                                          \
    CP_COMMIT(); } while (0)

#define CONSUME_CHUNK(CC) do {                                                 \
    const float* sbuf_ = smf + g * STG_WARP + ((CC) & 1) * STG_BUF;            \
    _Pragma("unroll")                                                          \
    for (int kt = 0; kt < 4; kt++) {                                           \
        _Pragma("unroll")                                                      \
        for (int rt = 0; rt < 4; rt++) {                                       \
            const float* ap = sbuf_ + (rt * 16 + r4) * 36 + kt * 8 + j;        \
            float f0 = ap[0];                                                  \
            float f2 = ap[4];                                                  \
            float f1 = ap[8 * 36];                                             \
            float f3 = ap[8 * 36 + 4];                                         \
            uint32_t ab0 = f2tf32(f0), ab1 = f2tf32(f1);                       \
            uint32_t ab2 = f2tf32(f2), ab3 = f2tf32(f3);                       \
            uint32_t as0 = f2tf32(f0 - __uint_as_float(ab0));                  \
            uint32_t as1 = f2tf32(f1 - __uint_as_float(ab1));                  \
            uint32_t as2 = f2tf32(f2 - __uint_as_float(ab2));                  \
            uint32_t as3 = f2tf32(f3 - __uint_as_float(ab3));                  \
            _Pragma("unroll")                                                  \
            for (int nt = 0; nt < 4; nt++) {                                   \
                mma_tf32(acc[rt][nt], ab0, ab1, ab2, ab3,                      \
                         bfr[(CC) * 4 + kt][nt][0], bfr[(CC) * 4 + kt][nt][1]); \
                mma_tf32(acc[rt][nt], as0, as1, as2, as3,                      \
                         bfr[(CC) * 4 + kt][nt][0], bfr[(CC) * 4 + kt][nt][1]); \
            }                                                                  \
        }                                                                      \
    } } while (0)

    for (int t = 0; t < T_STEPS; ++t) {
        // ---- prefetch gx for (erow, units 2eup,2eup+1) ----
        float gxv[8];
        {
            const float* gxr = g_gx + (size_t)t * BATCH * G4 + (size_t)erow * G4 + u0 + eup * 2;
#pragma unroll
            for (int gate = 0; gate < 4; gate++) {
                float2 v = __ldcg((const float2*)(gxr + gate * HID));
                gxv[0 * 4 + gate] = v.x;   // local unit 0 of pair
                gxv[1 * 4 + gate] = v.y;   // local unit 1 of pair
            }
        }

        if (t > 0) {
            const float* hsrc = g_h + (size_t)((t - 1) & 1) * (BATCH * HID);
            float acc[4][4][4];
#pragma unroll
            for (int rt = 0; rt < 4; rt++)
#pragma unroll
                for (int nt = 0; nt < 4; nt++)
#pragma unroll
                    for (int p = 0; p < 4; p++) acc[rt][nt][p] = 0.f;

            ISSUE_CHUNK(0);
            ISSUE_CHUNK(1);
            CP_WAIT(1); __syncwarp();
            CONSUME_CHUNK(0);
            ISSUE_CHUNK(2);
            CP_WAIT(1); __syncwarp();
            CONSUME_CHUNK(1);
            ISSUE_CHUNK(3);
            CP_WAIT(1); __syncwarp();
            CONSUME_CHUNK(2);
            CP_WAIT(0); __syncwarp();
            CONSUME_CHUNK(3);

            // ---- write partials to red[g] ----
            float* rw = smf + RED_OFF + g * RED_WARP;
#pragma unroll
            for (int rt = 0; rt < 4; rt++)
#pragma unroll
                for (int nt = 0; nt < 4; nt++) {
                    int r0 = rt * 16 + r4;
                    int c0 = nt * 8 + j * 2;
                    *(float2*)(rw + r0 * 34 + c0)       = make_float2(acc[rt][nt][0], acc[rt][nt][1]);
                    *(float2*)(rw + (r0 + 8) * 34 + c0) = make_float2(acc[rt][nt][2], acc[rt][nt][3]);
                }
        }
        __syncthreads();

        // ---- reduction + activations: thread = (erow, eup) -> 8 cols ----
        float pre[8];
#pragma unroll
        for (int loc = 0; loc < 8; loc++) {
            float s = gxv[loc];
            if (t > 0) {
                const float* rp = smf + RED_OFF + erow * 34 + eup * 8 + loc;
#pragma unroll
                for (int gg = 0; gg < 8; gg++) s += rp[gg * RED_WARP];
            }
            pre[loc] = s;
        }

        float h0, h1;
        {
            float fg = 1.f / (1.f + __expf(-pre[0]));
            float ig = 1.f / (1.f + __expf(-pre[1]));
            float gv = 2.f / (1.f + __expf(-2.f * pre[2])) - 1.f;
            float og = 1.f / (1.f + __expf(-pre[3]));
            float cn = fg * c_reg0 + ig * gv;
            c_reg0 = cn;
            h0 = og * (2.f / (1.f + __expf(-2.f * cn)) - 1.f);

            fg = 1.f / (1.f + __expf(-pre[4]));
            ig = 1.f / (1.f + __expf(-pre[5]));
            gv = 2.f / (1.f + __expf(-2.f * pre[6])) - 1.f;
            og = 1.f / (1.f + __expf(-pre[7]));
            cn = fg * c_reg1 + ig * gv;
            c_reg1 = cn;
            h1 = og * (2.f / (1.f + __expf(-2.f * cn)) - 1.f);
        }

        size_t hoff = (size_t)erow * HID + u0 + eup * 2;
        float* hdst = g_h + (size_t)(t & 1) * (BATCH * HID);
        *(float2*)(hdst + hoff) = make_float2(h0, h1);

        if (t < T_STEPS - 1) {
            grid_arrive(RB_BLOCKS, bar_s);
            *(float2*)(out + (size_t)t * (BATCH * HID) + hoff) = make_float2(h0, h1);
            grid_wait(bar_s);
        } else {
            *(float2*)(out + (size_t)t * (BATCH * HID) + hoff) = make_float2(h0, h1);
            long long base = (long long)T_STEPS * BATCH * HID;
            long long ho = base + (long long)hoff;
            long long co = base + (long long)(BATCH * HID) + (long long)hoff;
            if (ho + 1 < out_size) { out[ho] = h0; out[ho + 1] = h1; }
            if (co + 1 < out_size) { out[co] = c_reg0; out[co + 1] = c_reg1; }
        }
    }
#undef ISSUE_CHUNK
#undef CONSUME_CHUNK
}

// =====================================================================
extern "C" void kernel_launch(void* const* d_in, const int* in_sizes, int n_in,
                              void* d_out, int out_size)
{
    const float* inputs = (const float*)d_in[0];
    const float* Wf = (const float*)d_in[1];
    const float* bf = (const float*)d_in[2];
    const float* Wi = (const float*)d_in[3];
    const float* bi = (const float*)d_in[4];
    const float* Wg = (const float*)d_in[5];
    const float* bg = (const float*)d_in[6];
    const float* Wo = (const float*)d_in[7];
    const float* bo = (const float*)d_in[8];
    float* out = (float*)d_out;

    dim3 gridA(G4 / 128, (T_STEPS * BATCH) / 128);
    gemm_x_kernel<<<gridA, 256>>>(inputs, Wf, bf, Wi, bi, Wg, bg, Wo, bo);

    int smem_bytes = SMF_TOTAL * (int)sizeof(float);
    cudaFuncSetAttribute(lstm_rec_kernel, cudaFuncAttributeMaxDynamicSharedMemorySize, smem_bytes);
    lstm_rec_kernel<<<RB_BLOCKS, RB_THREADS, smem_bytes>>>(Wf, Wi, Wg, Wo, out, (long long)out_size);
}

// round 9
// speedup vs baseline: 5.3269x; 1.4606x over previous
#include <cuda_runtime.h>
#include <cstdint>
#include <math.h>

// Problem dims
#define T_STEPS 256
#define BATCH   64
#define DIM     512
#define HID     1024
#define G4      (4*HID)
#define KW      (DIM+HID)

// ---------------- device scratch ----------------
__device__ float g_gx[(size_t)T_STEPS * BATCH * G4];
__device__ float g_h[2 * BATCH * HID];
__device__ unsigned g_bar_count = 0;
__device__ volatile unsigned g_bar_sense = 0;

// ---------------- grid barrier (split arrive/wait) ----------------
__device__ __forceinline__ void grid_arrive(unsigned nblocks, unsigned& s) {
    __threadfence();
    __syncthreads();
    if (threadIdx.x == 0) {
        s = g_bar_sense;
        unsigned old = atomicAdd(&g_bar_count, 1u);
        if (old == nblocks - 1u) {
            g_bar_count = 0u;
            __threadfence();
            atomicAdd((unsigned*)&g_bar_sense, 1u);
        }
    }
}
__device__ __forceinline__ void grid_wait(unsigned s) {
    if (threadIdx.x == 0) {
        while (g_bar_sense == s) { __nanosleep(16); }
    }
    __syncthreads();
}

// ---------------- mma.sync tf32 helpers ----------------
__device__ __forceinline__ uint32_t smem_u32(const void* p) {
    uint32_t a;
    asm("{ .reg .u64 t; cvta.to.shared.u64 t, %1; cvt.u32.u64 %0, t; }" : "=r"(a) : "l"(p));
    return a;
}
__device__ __forceinline__ uint32_t f2tf32(float f) {
    uint32_t r;
    asm("cvt.rna.tf32.f32 %0, %1;" : "=r"(r) : "f"(f));
    return r;
}
__device__ __forceinline__ void mma_tf32(float* d,
                                         uint32_t a0, uint32_t a1, uint32_t a2, uint32_t a3,
                                         uint32_t b0, uint32_t b1) {
    asm volatile(
        "mma.sync.aligned.m16n8k8.row.col.f32.tf32.tf32.f32 "
        "{%0,%1,%2,%3}, {%4,%5,%6,%7}, {%8,%9}, {%0,%1,%2,%3};"
        : "+f"(d[0]), "+f"(d[1]), "+f"(d[2]), "+f"(d[3])
        : "r"(a0), "r"(a1), "r"(a2), "r"(a3), "r"(b0), "r"(b1));
}
__device__ __forceinline__ void cp16(uint32_t dst, const void* src) {
    asm volatile("cp.async.cg.shared.global [%0], [%1], 16;" :: "r"(dst), "l"(src));
}
__device__ __forceinline__ void cp16ca(uint32_t dst, const void* src) {
    asm volatile("cp.async.ca.shared.global [%0], [%1], 16;" :: "r"(dst), "l"(src));
}
#define CP_COMMIT() asm volatile("cp.async.commit_group;" ::: "memory")
#define CP_WAIT(n)  asm volatile("cp.async.wait_group %0;" :: "n"(n) : "memory")

// =====================================================================
// Phase A: gx = X @ Wx^T + b  via mma.sync tf32.
// BM=128, BN=128, BK=32, 256 threads (8 warps: 4 m-warps x 2 n-warps),
// warp tile m32 x n64, cp.async double-buffered tiles.
// =====================================================================
#define GA_BK 32
#define GA_STR 36                   // BK + 4 floats (conflict-free frags)
#define GA_ABUF (128 * GA_STR)      // floats per tile buffer
#define GA_SMEM (4 * GA_ABUF * 4)   // bytes: 2 A bufs + 2 B bufs = 73728

__global__ __launch_bounds__(256) void gemm_x_tc(
    const float* __restrict__ X,
    const float* __restrict__ Wf, const float* __restrict__ bfv,
    const float* __restrict__ Wi, const float* __restrict__ biv,
    const float* __restrict__ Wg, const float* __restrict__ bgv,
    const float* __restrict__ Wo, const float* __restrict__ bov)
{
    extern __shared__ float smf[];
    float* Asm = smf;                 // [2][128*GA_STR]
    float* Bsm = smf + 2 * GA_ABUF;   // [2][128*GA_STR]
    const uint32_t a_u32 = smem_u32(Asm);
    const uint32_t b_u32 = smem_u32(Bsm);

    const int tid  = threadIdx.x;
    const int w    = tid >> 5;
    const int lane = tid & 31;
    const int r4   = lane >> 2;
    const int j    = lane & 3;
    const int wm0  = (w & 3) * 32;
    const int wn0  = (w >> 2) * 64;

    const int m0 = blockIdx.y * 128;
    const int n0 = blockIdx.x * 128;
    const int gate = n0 >> 10;
    const int u0l  = n0 & 1023;

    const float* W    = (gate == 0) ? Wf  : (gate == 1) ? Wi  : (gate == 2) ? Wg  : Wo;
    const float* bias = (gate == 0) ? bfv : (gate == 1) ? biv : (gate == 2) ? bgv : bov;

    float acc[2][8][4];
#pragma unroll
    for (int mt = 0; mt < 2; mt++)
#pragma unroll
        for (int nt = 0; nt < 8; nt++)
#pragma unroll
            for (int p = 0; p < 4; p++) acc[mt][nt][p] = 0.f;

#define GA_LOAD(BUF, K0) do {                                                  \
    uint32_t ab = a_u32 + (uint32_t)((BUF) * GA_ABUF * 4);                     \
    uint32_t bb = b_u32 + (uint32_t)((BUF) * GA_ABUF * 4);                     \
    _Pragma("unroll")                                                          \
    for (int q = 0; q < 4; q++) {                                              \
        int idx = q * 256 + tid;                                               \
        int row = idx >> 3;                                                    \
        int kq = idx & 7;                                                      \
        uint32_t so = (uint32_t)((row * GA_STR + kq * 4) * 4);                 \
        cp16ca(ab + so, X + (size_t)(m0 + row) * DIM + (K0) + kq * 4);         \
        cp16ca(bb + so, W + (size_t)(u0l + row) * KW + (K0) + kq * 4);         \
    }                                                                          \
    CP_COMMIT(); } while (0)

    GA_LOAD(0, 0);
    int buf = 0;
#pragma unroll 1
    for (int k0 = 0; k0 < DIM; k0 += GA_BK) {
        if (k0 + GA_BK < DIM) { GA_LOAD(buf ^ 1, k0 + GA_BK); CP_WAIT(1); }
        else                  { CP_WAIT(0); }
        __syncthreads();

        const float* Ab = Asm + buf * GA_ABUF;
        const float* Bb = Bsm + buf * GA_ABUF;
#pragma unroll
        for (int kt = 0; kt < 4; kt++) {
            uint32_t a[2][4];
#pragma unroll
            for (int mt = 0; mt < 2; mt++) {
                const float* ap = Ab + (wm0 + mt * 16 + r4) * GA_STR + kt * 8 + j;
                a[mt][0] = f2tf32(ap[0]);
                a[mt][1] = f2tf32(ap[8 * GA_STR]);
                a[mt][2] = f2tf32(ap[4]);
                a[mt][3] = f2tf32(ap[8 * GA_STR + 4]);
            }
#pragma unroll
            for (int nt = 0; nt < 8; nt++) {
                const float* bp = Bb + (wn0 + nt * 8 + r4) * GA_STR + kt * 8 + j;
                uint32_t b0 = f2tf32(bp[0]);
                uint32_t b1 = f2tf32(bp[4]);
                mma_tf32(acc[0][nt], a[0][0], a[0][1], a[0][2], a[0][3], b0, b1);
                mma_tf32(acc[1][nt], a[1][0], a[1][1], a[1][2], a[1][3], b0, b1);
            }
        }
        __syncthreads();
        buf ^= 1;
    }
#undef GA_LOAD

    // epilogue: bias + store (cols 2j, 2j+1 contiguous -> float2)
#pragma unroll
    for (int nt = 0; nt < 8; nt++) {
        int gcol = wn0 + nt * 8 + 2 * j;
        float2 bb2 = *(const float2*)(bias + u0l + gcol);
#pragma unroll
        for (int mt = 0; mt < 2; mt++) {
            int gm = m0 + wm0 + mt * 16 + r4;
            float* d0 = g_gx + (size_t)gm * G4 + gate * HID + u0l + gcol;
            *(float2*)d0 = make_float2(acc[mt][nt][0] + bb2.x, acc[mt][nt][1] + bb2.y);
            float* d1 = d0 + 8 * G4;
            *(float2*)d1 = make_float2(acc[mt][nt][2] + bb2.x, acc[mt][nt][3] + bb2.y);
        }
    }
}

// =====================================================================
// Phase B: persistent recurrence, mma.sync tf32 (single-pass).
// 128 blocks x 256 threads (8 warps). Block owns 32 gate-cols; warp g owns
// K-slice [128g,128g+128) with register-resident weights; h staged via
// cp.async.cg double buffers; partials reduced through shared memory.
// =====================================================================
#define RB_BLOCKS 128
#define RB_THREADS 256

#define STG_BUF  (64 * 36)
#define STG_WARP (2 * STG_BUF)
#define RED_OFF  (8 * STG_WARP)
#define RED_WARP (64 * 34)
#define SMF_TOTAL (RED_OFF + 8 * RED_WARP)

__global__ __launch_bounds__(RB_THREADS, 1) void lstm_rec_kernel(
    const float* __restrict__ Wf, const float* __restrict__ Wi,
    const float* __restrict__ Wg, const float* __restrict__ Wo,
    float* __restrict__ out, long long out_size)
{
    extern __shared__ float smf[];
    const int tid  = threadIdx.x;
    const int g    = tid >> 5;
    const int lane = tid & 31;
    const int r4   = lane >> 2;
    const int j    = lane & 3;
    const int u0   = blockIdx.x * 8;

    const uint32_t stg_u32 = smem_u32(smf);

    // ---- register-resident weight fragments (tf32) ----
    uint32_t bfr[16][4][2];
#pragma unroll
    for (int nt = 0; nt < 4; nt++) {
        int col = nt * 8 + r4;
        int gate = col & 3;
        int ui = col >> 2;
        const float* Wq = (gate == 0) ? Wf : (gate == 1) ? Wi : (gate == 2) ? Wg : Wo;
        const float* wrow = Wq + (size_t)(u0 + ui) * KW + DIM + g * 128 + j;
#pragma unroll
        for (int kt = 0; kt < 16; kt++) {
            bfr[kt][nt][0] = f2tf32(__ldg(wrow + kt * 8));
            bfr[kt][nt][1] = f2tf32(__ldg(wrow + kt * 8 + 4));
        }
    }

    const int erow = tid >> 2;
    const int eup  = tid & 3;

    float c_reg0 = 0.f, c_reg1 = 0.f;
    unsigned bar_s = 0;

#define ISSUE_CHUNK(CC) do {                                                   \
    uint32_t dbase = stg_u32 + (uint32_t)((g * STG_WARP + ((CC) & 1) * STG_BUF) * 4); \
    const float* hs_ = hsrc + g * 128 + (CC) * 32;                             \
    _Pragma("unroll")                                                          \
    for (int q = 0; q < 16; q++) {                                             \
        int idx = q * 32 + lane;                                               \
        int row = idx >> 3;                                                    \
        int k4 = idx & 7;                                                      \
        cp16(dbase + (uint32_t)((row * 36 + k4 * 4) * 4),                      \
             hs_ + (size_t)row * HID + k4 * 4);                                \
    }                                                                          \
    CP_COMMIT(); } while (0)

#define CONSUME_CHUNK(CC) do {                                                 \
    const float* sbuf_ = smf + g * STG_WARP + ((CC) & 1) * STG_BUF;            \
    _Pragma("unroll")                                                          \
    for (int kt = 0; kt < 4; kt++) {                                           \
        _Pragma("unroll")                                                      \
        for (int rt = 0; rt < 4; rt++) {                                       \
            const float* ap = sbuf_ + (rt * 16 + r4) * 36 + kt * 8 + j;        \
            uint32_t a0 = f2tf32(ap[0]);                                       \
            uint32_t a2 = f2tf32(ap[4]);                                       \
            uint32_t a1 = f2tf32(ap[8 * 36]);                                  \
            uint32_t a3 = f2tf32(ap[8 * 36 + 4]);                              \
            _Pragma("unroll")                                                  \
            for (int nt = 0; nt < 4; nt++) {                                   \
                mma_tf32(acc[rt][nt], a0, a1, a2, a3,                          \
                         bfr[(CC) * 4 + kt][nt][0], bfr[(CC) * 4 + kt][nt][1]); \
            }                                                                  \
        }                                                                      \
    } } while (0)

    // gx prefetch for t=0
    float gxv[8];
    {
        const float* gxr = g_gx + (size_t)erow * G4 + u0 + eup * 2;
#pragma unroll
        for (int gate = 0; gate < 4; gate++) {
            float2 v = __ldcg((const float2*)(gxr + gate * HID));
            gxv[gate] = v.x;
            gxv[4 + gate] = v.y;
        }
    }

    for (int t = 0; t < T_STEPS; ++t) {
        if (t > 0) {
            const float* hsrc = g_h + (size_t)((t - 1) & 1) * (BATCH * HID);
            float acc[4][4][4];
#pragma unroll
            for (int rt = 0; rt < 4; rt++)
#pragma unroll
                for (int nt = 0; nt < 4; nt++)
#pragma unroll
                    for (int p = 0; p < 4; p++) acc[rt][nt][p] = 0.f;

            ISSUE_CHUNK(0);
            ISSUE_CHUNK(1);
            CP_WAIT(1); __syncwarp();
            CONSUME_CHUNK(0);
            ISSUE_CHUNK(2);
            CP_WAIT(1); __syncwarp();
            CONSUME_CHUNK(1);
            ISSUE_CHUNK(3);
            CP_WAIT(1); __syncwarp();
            CONSUME_CHUNK(2);
            CP_WAIT(0); __syncwarp();
            CONSUME_CHUNK(3);

            float* rw = smf + RED_OFF + g * RED_WARP;
#pragma unroll
            for (int rt = 0; rt < 4; rt++)
#pragma unroll
                for (int nt = 0; nt < 4; nt++) {
                    int r0 = rt * 16 + r4;
                    int c0 = nt * 8 + j * 2;
                    *(float2*)(rw + r0 * 34 + c0)       = make_float2(acc[rt][nt][0], acc[rt][nt][1]);
                    *(float2*)(rw + (r0 + 8) * 34 + c0) = make_float2(acc[rt][nt][2], acc[rt][nt][3]);
                }
        }
        __syncthreads();

        // ---- reduction + activations ----
        float pre[8];
#pragma unroll
        for (int loc = 0; loc < 8; loc++) {
            float s = gxv[loc >> 2 ? 4 + (loc & 3) : loc];  // placeholder, replaced below
            pre[loc] = s;
        }
        // (explicit, to keep gxv mapping clear: pre[gate]=unit0, pre[4+gate]=unit1)
#pragma unroll
        for (int loc = 0; loc < 8; loc++) {
            float s = gxv[loc];
            if (t > 0) {
                // red layout col = eup*8 + (unit_local*4 + gate); loc = unit_local*4+gate
                const float* rp = smf + RED_OFF + erow * 34 + eup * 8 + loc;
#pragma unroll
                for (int gg = 0; gg < 8; gg++) s += rp[gg * RED_WARP];
            }
            pre[loc] = s;
        }

        float h0, h1;
        {
            float fg = 1.f / (1.f + __expf(-pre[0]));
            float ig = 1.f / (1.f + __expf(-pre[1]));
            float gv = 2.f / (1.f + __expf(-2.f * pre[2])) - 1.f;
            float og = 1.f / (1.f + __expf(-pre[3]));
            float cn = fg * c_reg0 + ig * gv;
            c_reg0 = cn;
            h0 = og * (2.f / (1.f + __expf(-2.f * cn)) - 1.f);

            fg = 1.f / (1.f + __expf(-pre[4]));
            ig = 1.f / (1.f + __expf(-pre[5]));
            gv = 2.f / (1.f + __expf(-2.f * pre[6])) - 1.f;
            og = 1.f / (1.f + __expf(-pre[7]));
            cn = fg * c_reg1 + ig * gv;
            c_reg1 = cn;
            h1 = og * (2.f / (1.f + __expf(-2.f * cn)) - 1.f);
        }

        size_t hoff = (size_t)erow * HID + u0 + eup * 2;
        float* hdst = g_h + (size_t)(t & 1) * (BATCH * HID);
        *(float2*)(hdst + hoff) = make_float2(h0, h1);

        if (t < T_STEPS - 1) {
            grid_arrive(RB_BLOCKS, bar_s);
            *(float2*)(out + (size_t)t * (BATCH * HID) + hoff) = make_float2(h0, h1);
            // prefetch gx(t+1) during barrier window
            {
                const float* gxr = g_gx + (size_t)(t + 1) * BATCH * G4 + (size_t)erow * G4 + u0 + eup * 2;
#pragma unroll
                for (int gate = 0; gate < 4; gate++) {
                    float2 v = __ldcg((const float2*)(gxr + gate * HID));
                    gxv[gate] = v.x;
                    gxv[4 + gate] = v.y;
                }
            }
            grid_wait(bar_s);
        } else {
            *(float2*)(out + (size_t)t * (BATCH * HID) + hoff) = make_float2(h0, h1);
            long long base = (long long)T_STEPS * BATCH * HID;
            long long ho = base + (long long)hoff;
            long long co = base + (long long)(BATCH * HID) + (long long)hoff;
            if (ho + 1 < out_size) { out[ho] = h0; out[ho + 1] = h1; }
            if (co + 1 < out_size) { out[co] = c_reg0; out[co + 1] = c_reg1; }
        }
    }
#undef ISSUE_CHUNK
#undef CONSUME_CHUNK
}

// =====================================================================
extern "C" void kernel_launch(void* const* d_in, const int* in_sizes, int n_in,
                              void* d_out, int out_size)
{
    const float* inputs = (const float*)d_in[0];
    const float* Wf = (const float*)d_in[1];
    const float* bf = (const float*)d_in[2];
    const float* Wi = (const float*)d_in[3];
    const float* bi = (const float*)d_in[4];
    const float* Wg = (const float*)d_in[5];
    const float* bg = (const float*)d_in[6];
    const float* Wo = (const float*)d_in[7];
    const float* bo = (const float*)d_in[8];
    float* out = (float*)d_out;

    // Phase A: tensor-core GEMM for x-gates
    cudaFuncSetAttribute(gemm_x_tc, cudaFuncAttributeMaxDynamicSharedMemorySize, GA_SMEM);
    dim3 gridA(G4 / 128, (T_STEPS * BATCH) / 128);
    gemm_x_tc<<<gridA, 256, GA_SMEM>>>(inputs, Wf, bf, Wi, bi, Wg, bg, Wo, bo);

    // Phase B: persistent recurrence
    int smem_bytes = SMF_TOTAL * (int)sizeof(float);
    cudaFuncSetAttribute(lstm_rec_kernel, cudaFuncAttributeMaxDynamicSharedMemorySize, smem_bytes);
    lstm_rec_kernel<<<RB_BLOCKS, RB_THREADS, smem_bytes>>>(Wf, Wi, Wg, Wo, out, (long long)out_size);
}

// round 10
// speedup vs baseline: 5.5281x; 1.0378x over previous
#include <cuda_runtime.h>
#include <cstdint>
#include <math.h>

// Problem dims
#define T_STEPS 256
#define BATCH   64
#define DIM     512
#define HID     1024
#define G4      (4*HID)
#define KW      (DIM+HID)

// ---------------- device scratch ----------------
__device__ float g_gx[(size_t)T_STEPS * BATCH * G4];
__device__ float g_h[2 * BATCH * HID];
__device__ unsigned g_bar_count = 0;
__device__ volatile unsigned g_bar_sense = 0;
__device__ int g_flags[128 * 32];   // one 128B line per block, zero-init

// ---------------- atomic sense barrier (replay-safe, used once at end) ----------------
__device__ __forceinline__ void grid_bar_atomic(unsigned nblocks) {
    __threadfence();
    __syncthreads();
    if (threadIdx.x == 0) {
        unsigned s = g_bar_sense;
        unsigned old = atomicAdd(&g_bar_count, 1u);
        if (old == nblocks - 1u) {
            g_bar_count = 0u;
            __threadfence();
            atomicAdd((unsigned*)&g_bar_sense, 1u);
        } else {
            while (g_bar_sense == s) { __nanosleep(32); }
        }
    }
    __syncthreads();
}

// ---------------- mma.sync tf32 helpers ----------------
__device__ __forceinline__ uint32_t smem_u32(const void* p) {
    uint32_t a;
    asm("{ .reg .u64 t; cvta.to.shared.u64 t, %1; cvt.u32.u64 %0, t; }" : "=r"(a) : "l"(p));
    return a;
}
__device__ __forceinline__ uint32_t f2tf32(float f) {
    uint32_t r;
    asm("cvt.rna.tf32.f32 %0, %1;" : "=r"(r) : "f"(f));
    return r;
}
__device__ __forceinline__ void mma_tf32(float* d,
                                         uint32_t a0, uint32_t a1, uint32_t a2, uint32_t a3,
                                         uint32_t b0, uint32_t b1) {
    asm volatile(
        "mma.sync.aligned.m16n8k8.row.col.f32.tf32.tf32.f32 "
        "{%0,%1,%2,%3}, {%4,%5,%6,%7}, {%8,%9}, {%0,%1,%2,%3};"
        : "+f"(d[0]), "+f"(d[1]), "+f"(d[2]), "+f"(d[3])
        : "r"(a0), "r"(a1), "r"(a2), "r"(a3), "r"(b0), "r"(b1));
}
__device__ __forceinline__ void cp16(uint32_t dst, const void* src) {
    asm volatile("cp.async.cg.shared.global [%0], [%1], 16;" :: "r"(dst), "l"(src));
}
__device__ __forceinline__ void cp16ca(uint32_t dst, const void* src) {
    asm volatile("cp.async.ca.shared.global [%0], [%1], 16;" :: "r"(dst), "l"(src));
}
#define CP_COMMIT() asm volatile("cp.async.commit_group;" ::: "memory")
#define CP_WAIT(n)  asm volatile("cp.async.wait_group %0;" :: "n"(n) : "memory")

// =====================================================================
// Phase A: gx = X @ Wx^T + b  via mma.sync tf32.
// BM=128, BN=128, BK=32, 256 threads (8 warps: 4 m-warps x 2 n-warps),
// warp tile m32 x n64, cp.async double-buffered, 2 CTAs/SM.
// =====================================================================
#define GA_BK 32
#define GA_STR 36
#define GA_ABUF (128 * GA_STR)
#define GA_SMEM (4 * GA_ABUF * 4)

__global__ __launch_bounds__(256, 2) void gemm_x_tc(
    const float* __restrict__ X,
    const float* __restrict__ Wf, const float* __restrict__ bfv,
    const float* __restrict__ Wi, const float* __restrict__ biv,
    const float* __restrict__ Wg, const float* __restrict__ bgv,
    const float* __restrict__ Wo, const float* __restrict__ bov)
{
    extern __shared__ float smf[];
    float* Asm = smf;
    float* Bsm = smf + 2 * GA_ABUF;
    const uint32_t a_u32 = smem_u32(Asm);
    const uint32_t b_u32 = smem_u32(Bsm);

    const int tid  = threadIdx.x;
    const int w    = tid >> 5;
    const int lane = tid & 31;
    const int r4   = lane >> 2;
    const int j    = lane & 3;
    const int wm0  = (w & 3) * 32;
    const int wn0  = (w >> 2) * 64;

    const int m0 = blockIdx.y * 128;
    const int n0 = blockIdx.x * 128;
    const int gate = n0 >> 10;
    const int u0l  = n0 & 1023;

    const float* W    = (gate == 0) ? Wf  : (gate == 1) ? Wi  : (gate == 2) ? Wg  : Wo;
    const float* bias = (gate == 0) ? bfv : (gate == 1) ? biv : (gate == 2) ? bgv : bov;

    float acc[2][8][4];
#pragma unroll
    for (int mt = 0; mt < 2; mt++)
#pragma unroll
        for (int nt = 0; nt < 8; nt++)
#pragma unroll
            for (int p = 0; p < 4; p++) acc[mt][nt][p] = 0.f;

#define GA_LOAD(BUF, K0) do {                                                  \
    uint32_t ab = a_u32 + (uint32_t)((BUF) * GA_ABUF * 4);                     \
    uint32_t bb = b_u32 + (uint32_t)((BUF) * GA_ABUF * 4);                     \
    _Pragma("unroll")                                                          \
    for (int q = 0; q < 4; q++) {                                              \
        int idx = q * 256 + tid;                                               \
        int row = idx >> 3;                                                    \
        int kq = idx & 7;                                                      \
        uint32_t so = (uint32_t)((row * GA_STR + kq * 4) * 4);                 \
        cp16ca(ab + so, X + (size_t)(m0 + row) * DIM + (K0) + kq * 4);         \
        cp16ca(bb + so, W + (size_t)(u0l + row) * KW + (K0) + kq * 4);         \
    }                                                                          \
    CP_COMMIT(); } while (0)

    GA_LOAD(0, 0);
    int buf = 0;
#pragma unroll 1
    for (int k0 = 0; k0 < DIM; k0 += GA_BK) {
        if (k0 + GA_BK < DIM) { GA_LOAD(buf ^ 1, k0 + GA_BK); CP_WAIT(1); }
        else                  { CP_WAIT(0); }
        __syncthreads();

        const float* Ab = Asm + buf * GA_ABUF;
        const float* Bb = Bsm + buf * GA_ABUF;
#pragma unroll
        for (int kt = 0; kt < 4; kt++) {
            uint32_t a[2][4];
#pragma unroll
            for (int mt = 0; mt < 2; mt++) {
                const float* ap = Ab + (wm0 + mt * 16 + r4) * GA_STR + kt * 8 + j;
                a[mt][0] = f2tf32(ap[0]);
                a[mt][1] = f2tf32(ap[8 * GA_STR]);
                a[mt][2] = f2tf32(ap[4]);
                a[mt][3] = f2tf32(ap[8 * GA_STR + 4]);
            }
#pragma unroll
            for (int nt = 0; nt < 8; nt++) {
                const float* bp = Bb + (wn0 + nt * 8 + r4) * GA_STR + kt * 8 + j;
                uint32_t b0 = f2tf32(bp[0]);
                uint32_t b1 = f2tf32(bp[4]);
                mma_tf32(acc[0][nt], a[0][0], a[0][1], a[0][2], a[0][3], b0, b1);
                mma_tf32(acc[1][nt], a[1][0], a[1][1], a[1][2], a[1][3], b0, b1);
            }
        }
        __syncthreads();
        buf ^= 1;
    }
#undef GA_LOAD

#pragma unroll
    for (int nt = 0; nt < 8; nt++) {
        int gcol = wn0 + nt * 8 + 2 * j;
        float2 bb2 = *(const float2*)(bias + u0l + gcol);
#pragma unroll
        for (int mt = 0; mt < 2; mt++) {
            int gm = m0 + wm0 + mt * 16 + r4;
            float* d0 = g_gx + (size_t)gm * G4 + gate * HID + u0l + gcol;
            *(float2*)d0 = make_float2(acc[mt][nt][0] + bb2.x, acc[mt][nt][1] + bb2.y);
            float* d1 = d0 + 8 * G4;
            *(float2*)d1 = make_float2(acc[mt][nt][2] + bb2.x, acc[mt][nt][3] + bb2.y);
        }
    }
}

// =====================================================================
// Phase B: persistent recurrence, mma.sync tf32, flag-based grid barrier.
// =====================================================================
#define RB_BLOCKS 128
#define RB_THREADS 256

#define STG_BUF  (64 * 36)
#define STG_WARP (2 * STG_BUF)
#define RED_OFF  (8 * STG_WARP)
#define RED_WARP (64 * 34)
#define SMF_TOTAL (RED_OFF + 8 * RED_WARP)

__global__ __launch_bounds__(RB_THREADS, 1) void lstm_rec_kernel(
    const float* __restrict__ Wf, const float* __restrict__ Wi,
    const float* __restrict__ Wg, const float* __restrict__ Wo,
    float* __restrict__ out, long long out_size)
{
    extern __shared__ float smf[];
    const int tid  = threadIdx.x;
    const int g    = tid >> 5;
    const int lane = tid & 31;
    const int r4   = lane >> 2;
    const int j    = lane & 3;
    const int u0   = blockIdx.x * 8;

    const uint32_t stg_u32 = smem_u32(smf);

    // ---- register-resident weight fragments (tf32) ----
    uint32_t bfr[16][4][2];
#pragma unroll
    for (int nt = 0; nt < 4; nt++) {
        int col = nt * 8 + r4;
        int gate = col & 3;
        int ui = col >> 2;
        const float* Wq = (gate == 0) ? Wf : (gate == 1) ? Wi : (gate == 2) ? Wg : Wo;
        const float* wrow = Wq + (size_t)(u0 + ui) * KW + DIM + g * 128 + j;
#pragma unroll
        for (int kt = 0; kt < 16; kt++) {
            bfr[kt][nt][0] = f2tf32(__ldg(wrow + kt * 8));
            bfr[kt][nt][1] = f2tf32(__ldg(wrow + kt * 8 + 4));
        }
    }

    const int erow = tid >> 2;
    const int eup  = tid & 3;

    float c_reg0 = 0.f, c_reg1 = 0.f;

#define ISSUE_CHUNK(CC) do {                                                   \
    uint32_t dbase = stg_u32 + (uint32_t)((g * STG_WARP + ((CC) & 1) * STG_BUF) * 4); \
    const float* hs_ = hsrc + g * 128 + (CC) * 32;                             \
    _Pragma("unroll")                                                          \
    for (int q = 0; q < 16; q++) {                                             \
        int idx = q * 32 + lane;                                               \
        int row = idx >> 3;                                                    \
        int k4 = idx & 7;                                                      \
        cp16(dbase + (uint32_t)((row * 36 + k4 * 4) * 4),                      \
             hs_ + (size_t)row * HID + k4 * 4);                                \
    }                                                                          \
    CP_COMMIT(); } while (0)

#define CONSUME_CHUNK(CC) do {                                                 \
    const float* sbuf_ = smf + g * STG_WARP + ((CC) & 1) * STG_BUF;            \
    _Pragma("unroll")                                                          \
    for (int kt = 0; kt < 4; kt++) {                                           \
        _Pragma("unroll")                                                      \
        for (int rt = 0; rt < 4; rt++) {                                       \
            const float* ap = sbuf_ + (rt * 16 + r4) * 36 + kt * 8 + j;        \
            uint32_t a0 = f2tf32(ap[0]);                                       \
            uint32_t a2 = f2tf32(ap[4]);                                       \
            uint32_t a1 = f2tf32(ap[8 * 36]);                                  \
            uint32_t a3 = f2tf32(ap[8 * 36 + 4]);                              \
            _Pragma("unroll")                                                  \
            for (int nt = 0; nt < 4; nt++) {                                   \
                mma_tf32(acc[rt][nt], a0, a1, a2, a3,                          \
                         bfr[(CC) * 4 + kt][nt][0], bfr[(CC) * 4 + kt][nt][1]); \
            }                                                                  \
        }                                                                      \
    } } while (0)

    // gx prefetch for t=0
    float gxv[8];
    {
        const float* gxr = g_gx + (size_t)erow * G4 + u0 + eup * 2;
#pragma unroll
        for (int gate = 0; gate < 4; gate++) {
            float2 v = __ldcg((const float2*)(gxr + gate * HID));
            gxv[gate] = v.x;
            gxv[4 + gate] = v.y;
        }
    }

    int* const my_flag = g_flags + blockIdx.x * 32;

    for (int t = 0; t < T_STEPS; ++t) {
        if (t > 0) {
            const float* hsrc = g_h + (size_t)((t - 1) & 1) * (BATCH * HID);
            float acc[4][4][4];
#pragma unroll
            for (int rt = 0; rt < 4; rt++)
#pragma unroll
                for (int nt = 0; nt < 4; nt++)
#pragma unroll
                    for (int p = 0; p < 4; p++) acc[rt][nt][p] = 0.f;

            ISSUE_CHUNK(0);
            ISSUE_CHUNK(1);
            CP_WAIT(1); __syncwarp();
            CONSUME_CHUNK(0);
            ISSUE_CHUNK(2);
            CP_WAIT(1); __syncwarp();
            CONSUME_CHUNK(1);
            ISSUE_CHUNK(3);
            CP_WAIT(1); __syncwarp();
            CONSUME_CHUNK(2);
            CP_WAIT(0); __syncwarp();
            CONSUME_CHUNK(3);

            float* rw = smf + RED_OFF + g * RED_WARP;
#pragma unroll
            for (int rt = 0; rt < 4; rt++)
#pragma unroll
                for (int nt = 0; nt < 4; nt++) {
                    int r0 = rt * 16 + r4;
                    int c0 = nt * 8 + j * 2;
                    *(float2*)(rw + r0 * 34 + c0)       = make_float2(acc[rt][nt][0], acc[rt][nt][1]);
                    *(float2*)(rw + (r0 + 8) * 34 + c0) = make_float2(acc[rt][nt][2], acc[rt][nt][3]);
                }
        }
        __syncthreads();

        // ---- reduction + activations (pre[gate]=unit0, pre[4+gate]=unit1) ----
        float pre[8];
#pragma unroll
        for (int loc = 0; loc < 8; loc++) {
            float s = gxv[loc];
            if (t > 0) {
                const float* rp = smf + RED_OFF + erow * 34 + eup * 8 + loc;
#pragma unroll
                for (int gg = 0; gg < 8; gg++) s += rp[gg * RED_WARP];
            }
            pre[loc] = s;
        }

        float h0, h1;
        {
            float fg = 1.f / (1.f + __expf(-pre[0]));
            float ig = 1.f / (1.f + __expf(-pre[1]));
            float gv = 2.f / (1.f + __expf(-2.f * pre[2])) - 1.f;
            float og = 1.f / (1.f + __expf(-pre[3]));
            float cn = fg * c_reg0 + ig * gv;
            c_reg0 = cn;
            h0 = og * (2.f / (1.f + __expf(-2.f * cn)) - 1.f);

            fg = 1.f / (1.f + __expf(-pre[4]));
            ig = 1.f / (1.f + __expf(-pre[5]));
            gv = 2.f / (1.f + __expf(-2.f * pre[6])) - 1.f;
            og = 1.f / (1.f + __expf(-pre[7]));
            cn = fg * c_reg1 + ig * gv;
            c_reg1 = cn;
            h1 = og * (2.f / (1.f + __expf(-2.f * cn)) - 1.f);
        }

        size_t hoff = (size_t)erow * HID + u0 + eup * 2;
        float* hdst = g_h + (size_t)(t & 1) * (BATCH * HID);
        *(float2*)(hdst + hoff) = make_float2(h0, h1);

        if (t < T_STEPS - 1) {
            // ---- flag barrier: publish h, then signal own flag ----
            __threadfence();
            __syncthreads();
            if (tid == 0) {
                __threadfence();
                asm volatile("st.global.cg.u32 [%0], %1;" :: "l"(my_flag), "r"(t + 1) : "memory");
            }
            // overlap: out store + gx(t+1) prefetch during barrier window
            *(float2*)(out + (size_t)t * (BATCH * HID) + hoff) = make_float2(h0, h1);
            {
                const float* gxr = g_gx + (size_t)(t + 1) * BATCH * G4 + (size_t)erow * G4 + u0 + eup * 2;
#pragma unroll
                for (int gate = 0; gate < 4; gate++) {
                    float2 v = __ldcg((const float2*)(gxr + gate * HID));
                    gxv[gate] = v.x;
                    gxv[4 + gate] = v.y;
                }
            }
            // ---- poll: thread b waits on block b's flag ----
            if (tid < RB_BLOCKS) {
                const int* fp = g_flags + tid * 32;
                int v;
                while (true) {
                    asm volatile("ld.global.cg.u32 %0, [%1];" : "=r"(v) : "l"(fp) : "memory");
                    if (v >= t + 1) break;
                    __nanosleep(16);
                }
                __threadfence();   // acquire: order h reads after flag observation
            }
            __syncthreads();
        } else {
            *(float2*)(out + (size_t)t * (BATCH * HID) + hoff) = make_float2(h0, h1);
            long long base = (long long)T_STEPS * BATCH * HID;
            long long ho = base + (long long)hoff;
            long long co = base + (long long)(BATCH * HID) + (long long)hoff;
            if (ho + 1 < out_size) { out[ho] = h0; out[ho + 1] = h1; }
            if (co + 1 < out_size) { out[co] = c_reg0; out[co + 1] = c_reg1; }
        }
    }
#undef ISSUE_CHUNK
#undef CONSUME_CHUNK

    // ---- replay-safe cleanup: everyone past all polls, then reset flags ----
    grid_bar_atomic(RB_BLOCKS);
    if (tid == 0) {
        asm volatile("st.global.cg.u32 [%0], %1;" :: "l"(my_flag), "r"(0) : "memory");
    }
}

// =====================================================================
extern "C" void kernel_launch(void* const* d_in, const int* in_sizes, int n_in,
                              void* d_out, int out_size)
{
    const float* inputs = (const float*)d_in[0];
    const float* Wf = (const float*)d_in[1];
    const float* bf = (const float*)d_in[2];
    const float* Wi = (const float*)d_in[3];
    const float* bi = (const float*)d_in[4];
    const float* Wg = (const float*)d_in[5];
    const float* bg = (const float*)d_in[6];
    const float* Wo = (const float*)d_in[7];
    const float* bo = (const float*)d_in[8];
    float* out = (float*)d_out;

    cudaFuncSetAttribute(gemm_x_tc, cudaFuncAttributeMaxDynamicSharedMemorySize, GA_SMEM);
    dim3 gridA(G4 / 128, (T_STEPS * BATCH) / 128);
    gemm_x_tc<<<gridA, 256, GA_SMEM>>>(inputs, Wf, bf, Wi, bi, Wg, bg, Wo, bo);

    int smem_bytes = SMF_TOTAL * (int)sizeof(float);
    cudaFuncSetAttribute(lstm_rec_kernel, cudaFuncAttributeMaxDynamicSharedMemorySize, smem_bytes);
    lstm_rec_kernel<<<RB_BLOCKS, RB_THREADS, smem_bytes>>>(Wf, Wi, Wg, Wo, out, (long long)out_size);
}